// round 7
// baseline (speedup 1.0000x reference)
#include <cuda_runtime.h>
#include <math.h>

#define NB 4
#define NA 262144
#define PRE 4000
#define POST 1000
#define NBIN 16384
#define BSHIFT 18
#define KCAP 8192
#define PCAP 8192
#define G 128
#define T 256
#define CPB (G / NB)            // 32 CTAs per batch
#define CHUNK4 (NA / CPB / 4)   // 2048 float4 per CTA slice

static __device__ const float NMS_TH = 0.3f;
static __device__ const float AUG = 0.2f;

// ---- global scratch (zero-init; tail phase re-zeroes everything dirtied) ----
__device__ unsigned g_hist[NB][NBIN];
__device__ unsigned g_bincnt[NB][NBIN];
__device__ int g_base[NB][NBIN];
__device__ unsigned g_selbin[NB];
__device__ int g_cc[NB];
__device__ unsigned long long g_keys2[NB][KCAP];
__device__ float g_geo[NB][7][PRE];
__device__ float g_box[NB][PRE][7];
__device__ float g_score[NB][PRE];
__device__ unsigned g_pairs[NB][PCAP];
__device__ int g_pcnt[NB];
__device__ int g_count;
__device__ volatile int g_sense;

__device__ __forceinline__ unsigned mapf(float v) {
    unsigned u = __float_as_uint(v);
    return (u & 0x80000000u) ? ~u : (u | 0x80000000u);
}
__device__ __forceinline__ float unmapf(unsigned m) {
    return __uint_as_float((m & 0x80000000u) ? (m & 0x7FFFFFFFu) : ~m);
}

__device__ __forceinline__ void decode_box(const float* __restrict__ rg,
                                           const float* __restrict__ an,
                                           float* bx) {
    float xa = an[0], ya = an[1], za = an[2];
    float wa = an[3], la = an[4], ha = an[5], ra = an[6];
    float diag = sqrtf(wa * wa + la * la);
    bx[0] = rg[0] * diag + xa;
    bx[1] = rg[1] * diag + ya;
    bx[2] = rg[2] * ha + za;
    bx[3] = expf(rg[3]) * wa;
    bx[4] = expf(rg[4]) * la;
    bx[5] = expf(rg[5]) * ha;
    bx[6] = rg[6] + ra;
}

// sense-reversing grid barrier; MUST execute an even count per kernel call
__device__ __forceinline__ void gsync(int& local_sense) {
    __syncthreads();
    if (threadIdx.x == 0) {
        int ls = local_sense ^ 1;
        local_sense = ls;
        __threadfence();
        if (atomicAdd(&g_count, 1) == (int)gridDim.x - 1) {
            g_count = 0;
            __threadfence();
            g_sense = ls;
        } else {
            while (g_sense != ls) { }
        }
    }
    __syncthreads();
}

__global__ void __launch_bounds__(T) rpn_mega(
    const float* __restrict__ obj,
    const float* __restrict__ reg,
    const float* __restrict__ anc,
    float* __restrict__ out)
{
    extern __shared__ unsigned char dynsm[];   // 64 KB, reused per phase
    const int cta = blockIdx.x;
    const int tid = threadIdx.x;
    int ls = 0;   // barrier sense (only tid 0's copy matters)

    // ========== phase 1: 14-bit smem histogram ==========
    {
        unsigned* sh = (unsigned*)dynsm;
        for (int i = tid; i < NBIN; i += T) sh[i] = 0u;
        __syncthreads();
        const int b = cta / CPB;
        const int c = cta % CPB;
        const float4* o4 = (const float4*)(obj + (size_t)b * NA) + (size_t)c * CHUNK4;
        for (int i = tid; i < CHUNK4; i += T) {
            float4 v = o4[i];
            atomicAdd(&sh[mapf(v.x) >> BSHIFT], 1u);
            atomicAdd(&sh[mapf(v.y) >> BSHIFT], 1u);
            atomicAdd(&sh[mapf(v.z) >> BSHIFT], 1u);
            atomicAdd(&sh[mapf(v.w) >> BSHIFT], 1u);
        }
        __syncthreads();
        for (int i = tid; i < NBIN; i += T) {
            unsigned cnt = sh[i];
            if (cnt) atomicAdd(&g_hist[b][i], cnt);
        }
    }
    gsync(ls);   // B1

    // ========== phase 2: suffix-sum base[] + selbin + cc (CTAs 0..3) ==========
    if (cta < NB) {
        const int b = cta;
        __shared__ unsigned ssum[T];
        const unsigned* h = g_hist[b];
        const int CW = NBIN / T;   // 64
        const int bi = tid * CW;
        unsigned csum = 0;
        for (int k = 0; k < CW; ++k) csum += h[bi + k];
        unsigned orig = csum;
        ssum[tid] = csum;
        __syncthreads();
        for (int d = 1; d < T; d <<= 1) {
            unsigned v = (tid + d < T) ? ssum[tid + d] : 0u;
            __syncthreads();
            ssum[tid] += v;
            __syncthreads();
        }
        unsigned run = ssum[tid] - orig;   // count strictly above this chunk
        for (int k = CW - 1; k >= 0; --k) {
            int bin = bi + k;
            unsigned cnt = h[bin];
            g_base[b][bin] = (int)run;
            unsigned nb2 = run + cnt;
            if (run < PRE && nb2 >= PRE) {
                g_selbin[b] = (unsigned)bin;
                g_cc[b] = (int)(nb2 < KCAP ? nb2 : KCAP);
            }
            run = nb2;
        }
    }
    gsync(ls);   // B2

    // ========== phase 3: binned scatter of candidates ==========
    {
        const int b = cta / CPB;
        const int c = cta % CPB;
        const unsigned Th = g_selbin[b] << BSHIFT;
        const float4* o4 = (const float4*)(obj + (size_t)b * NA) + (size_t)c * CHUNK4;
        for (int i = tid; i < CHUNK4; i += T) {
            float4 v = o4[i];
            unsigned uu[4] = {mapf(v.x), mapf(v.y), mapf(v.z), mapf(v.w)};
            int e0 = (c * CHUNK4 + i) * 4;
            #pragma unroll
            for (int q = 0; q < 4; ++q) {
                if (uu[q] >= Th) {
                    int bin = uu[q] >> BSHIFT;
                    int slot = g_base[b][bin] + (int)atomicAdd(&g_bincnt[b][bin], 1u);
                    if (slot < KCAP)
                        g_keys2[b][slot] =
                            ((unsigned long long)uu[q] << 32) | (unsigned)(~(e0 + q));
                }
            }
        }
    }
    gsync(ls);   // B3

    // ========== phase 4: two-level exact rank + decode + scatter ==========
    {
        const int b = cta / CPB;
        const int s = (cta % CPB) * T + tid;   // covers [0, 8192) = KCAP
        const int cc = g_cc[b];
        if (s < cc) {
            const unsigned long long me = g_keys2[b][s];
            const unsigned u = (unsigned)(me >> 32);
            const int bin = (int)(u >> BSHIFT);
            const int lo = g_base[b][bin];
            int hi = lo + (int)g_hist[b][bin];
            if (hi > cc) hi = cc;
            int rank = lo;
            for (int t2 = lo; t2 < hi; ++t2) rank += (g_keys2[b][t2] > me);

            if (rank < PRE) {
                int idx = (int)(~(unsigned)(me & 0xFFFFFFFFull));
                const float* rg = reg + ((size_t)b * NA + idx) * 7;
                const float* an = anc + ((size_t)b * NA + idx) * 7;
                float bx[7];
                decode_box(rg, an, bx);
                #pragma unroll
                for (int q = 0; q < 7; ++q) g_box[b][rank][q] = bx[q];
                g_score[b][rank] = 1.0f / (1.0f + expf(-unmapf(u)));
                float sx = fmaxf(bx[3], AUG);
                float sy = fmaxf(bx[4], AUG);
                float sz = fmaxf(bx[5], AUG);
                g_geo[b][0][rank] = bx[0] - sx * 0.5f;
                g_geo[b][1][rank] = bx[1] - sy * 0.5f;
                g_geo[b][2][rank] = bx[2];
                g_geo[b][3][rank] = bx[0] + sx * 0.5f;
                g_geo[b][4][rank] = bx[1] + sy * 0.5f;
                g_geo[b][5][rank] = bx[2] + sz;
                g_geo[b][6][rank] = sx * sy * sz;
            }
        }
    }
    gsync(ls);   // B4

    // ========== phase 5: conflict-pair discovery ==========
    {
        float (*s)[T] = (float(*)[T])dynsm;   // 7*256*4 = 7 KB
        const int NJ = 16;                     // ceil(PRE/256)
        const int NU = NB * NJ * 4;            // 256 units
        for (int u = cta; u < NU; u += G) {
            const int b = u >> 6;
            const int jb = (u >> 2) & 15;
            const int ic = u & 3;
            const int j = jb * T + tid;
            const int jmax = min(PRE, (jb + 1) * T);
            const int i_lo = ic * 1024;
            const int i_hi = min(min((ic + 1) * 1024, PRE), jmax);
            if (i_lo >= i_hi) continue;
            const bool active = (j < PRE);
            float jlx = 0, jly = 0, jlz = 0, jhx = 0, jhy = 0, jhz = 0, jv = 0;
            if (active) {
                jlx = g_geo[b][0][j]; jly = g_geo[b][1][j]; jlz = g_geo[b][2][j];
                jhx = g_geo[b][3][j]; jhy = g_geo[b][4][j]; jhz = g_geo[b][5][j];
                jv  = g_geo[b][6][j];
            }
            for (int i0 = i_lo; i0 < i_hi; i0 += T) {
                int ii = i0 + tid;
                if (ii < i_hi) {
                    #pragma unroll
                    for (int q = 0; q < 7; ++q) s[q][tid] = g_geo[b][q][ii];
                }
                __syncthreads();
                if (active) {
                    int lim = min(T, i_hi - i0);
                    for (int k = 0; k < lim; ++k) {
                        int i = i0 + k;
                        if (i >= j) break;
                        float dxx = fminf(jhx, s[3][k]) - fmaxf(jlx, s[0][k]);
                        if (dxx <= 0.f) continue;
                        float dyy = fminf(jhy, s[4][k]) - fmaxf(jly, s[1][k]);
                        if (dyy <= 0.f) continue;
                        float dzz = fminf(jhz, s[5][k]) - fmaxf(jlz, s[2][k]);
                        if (dzz <= 0.f) continue;
                        float inter = dxx * dyy * dzz;
                        float iou = inter / fmaxf(jv + s[6][k] - inter, 1e-8f);
                        if (iou > NMS_TH) {
                            int p = atomicAdd(&g_pcnt[b], 1);
                            if (p < PCAP)
                                g_pairs[b][p] = ((unsigned)i << 16) | (unsigned)j;
                        }
                    }
                }
                __syncthreads();
            }
        }
    }
    gsync(ls);   // B5

    // ========== phase 6: resolve + output (CTAs 0..3) / rezero (CTAs 4..127) ==========
    if (cta < NB) {
        const int b = cta;
        unsigned* pr = (unsigned*)dynsm;                     // 32 KB
        int* order = (int*)(dynsm + PCAP * 4);               // 4000 B
        __shared__ unsigned keepw[128];
        __shared__ int scan[126];
        __shared__ int s_nk;

        int m = g_pcnt[b];
        if (m > PCAP) m = PCAP;
        int n2 = 32;
        while (n2 < m) n2 <<= 1;
        for (int i = tid; i < n2; i += T) pr[i] = (i < m) ? g_pairs[b][i] : 0xFFFFFFFFu;
        __syncthreads();

        for (int k = 2; k <= n2; k <<= 1) {
            for (int jj = k >> 1; jj > 0; jj >>= 1) {
                for (int t2 = tid; t2 < n2; t2 += T) {
                    int ixj = t2 ^ jj;
                    if (ixj > t2) {
                        unsigned a = pr[t2], c2 = pr[ixj];
                        bool up = ((t2 & k) == 0);
                        if (up ? (a > c2) : (a < c2)) { pr[t2] = c2; pr[ixj] = a; }
                    }
                }
                __syncthreads();
            }
        }

        for (int t2 = tid; t2 < 128; t2 += T) keepw[t2] = 0xFFFFFFFFu;
        __syncthreads();

        if (tid == 0) {
            for (int p = 0; p < m; ++p) {
                unsigned u = pr[p];
                int i = (int)(u >> 16);
                int j = (int)(u & 0xFFFFu);
                if ((keepw[i >> 5] >> (i & 31)) & 1u)
                    keepw[j >> 5] &= ~(1u << (j & 31));
            }
            int run = 0;
            for (int w = 0; w < 125; ++w) {
                scan[w] = run;
                run += __popc(keepw[w]);
            }
            s_nk = run < POST ? run : POST;
            g_pcnt[b] = 0;   // rezero (owned by this CTA; rezero CTAs skip it)
        }
        __syncthreads();

        if (tid < 125) {
            unsigned w = keepw[tid];
            int base = scan[tid];
            while (w && base < POST) {
                int l = __ffs(w) - 1;
                w &= w - 1;
                order[base] = tid * 32 + l;
                ++base;
            }
        }
        __syncthreads();

        const int nk = s_nk;
        float* outb = out + (size_t)b * POST * 8;
        for (int r = tid; r < POST; r += T) {
            float row[8];
            if (r < nk) {
                int rr = order[r];
                #pragma unroll
                for (int q = 0; q < 7; ++q) row[q] = g_box[b][rr][q];
                row[7] = g_score[b][rr];
            } else {
                #pragma unroll
                for (int q = 0; q < 8; ++q) row[q] = 0.f;
            }
            float4* o4 = (float4*)(outb + (size_t)r * 8);
            o4[0] = make_float4(row[0], row[1], row[2], row[3]);
            o4[1] = make_float4(row[4], row[5], row[6], row[7]);
        }
    } else {
        // rezero hist + bincnt for the next replay
        unsigned* h1 = &g_hist[0][0];
        unsigned* h2 = &g_bincnt[0][0];
        const int n = NB * NBIN;
        const int nth = (G - NB) * T;
        for (int i = (cta - NB) * T + tid; i < n; i += nth) {
            h1[i] = 0u;
            h2[i] = 0u;
        }
    }
    gsync(ls);   // B6 (keeps barrier count even -> sense returns to 0 for next replay)
}

extern "C" void kernel_launch(void* const* d_in, const int* in_sizes, int n_in,
                              void* d_out, int out_size) {
    const float* obj = (const float*)d_in[0];
    const float* reg = (const float*)d_in[1];
    const float* anc = (const float*)d_in[2];
    float* out = (float*)d_out;

    cudaFuncSetAttribute(rpn_mega, cudaFuncAttributeMaxDynamicSharedMemorySize,
                         NBIN * 4);
    rpn_mega<<<G, T, NBIN * 4>>>(obj, reg, anc, out);
}

// round 8
// speedup vs baseline: 1.9199x; 1.9199x over previous
#include <cuda_runtime.h>
#include <math.h>

#define NB 4
#define NA 262144
#define PRE 4000
#define POST 1000
#define NBIN 16384
#define BSHIFT 18
#define KCAP 8192
#define HCTA 64
#define HTHR 256
#define SCTA 128
#define STHR 256
#define RTHR 256
#define RCTA (KCAP / RTHR)
#define PCAP 8192

static __device__ const float NMS_TH = 0.3f;
static __device__ const float AUG = 0.2f;

// ---- global scratch (zero-init; k_final re-zeroes everything dirtied) ----
__device__ unsigned g_hist[NB][NBIN];
__device__ unsigned g_bincnt[NB][NBIN];
__device__ int g_base[NB][NBIN];
__device__ unsigned g_selbin[NB];
__device__ int g_cc[NB];
__device__ int g_done[NB];
__device__ unsigned long long g_keys2[NB][KCAP];
__device__ float4 g_geoA[NB][PRE];   // lox, hix, loy, hiy
__device__ float4 g_geoB[NB][PRE];   // loz, hiz, vol, 0
__device__ float g_box[NB][PRE][7];
__device__ float g_score[NB][PRE];
__device__ unsigned g_pairs[NB][PCAP];
__device__ int g_pcnt[NB];

__device__ __forceinline__ unsigned mapf(float v) {
    unsigned u = __float_as_uint(v);
    return (u & 0x80000000u) ? ~u : (u | 0x80000000u);
}
__device__ __forceinline__ float unmapf(unsigned m) {
    return __uint_as_float((m & 0x80000000u) ? (m & 0x7FFFFFFFu) : ~m);
}

__device__ __forceinline__ void decode_box(const float* __restrict__ rg,
                                           const float* __restrict__ an,
                                           float* bx) {
    float xa = an[0], ya = an[1], za = an[2];
    float wa = an[3], la = an[4], ha = an[5], ra = an[6];
    float diag = sqrtf(wa * wa + la * la);
    bx[0] = rg[0] * diag + xa;
    bx[1] = rg[1] * diag + ya;
    bx[2] = rg[2] * ha + za;
    bx[3] = expf(rg[3]) * wa;
    bx[4] = expf(rg[4]) * la;
    bx[5] = expf(rg[5]) * ha;
    bx[6] = rg[6] + ra;
}

// ================= K1: smem histogram + last-CTA inline suffix scan =================
__global__ void __launch_bounds__(HTHR) k_hist(const float* __restrict__ obj) {
    __shared__ unsigned sh[NBIN];
    __shared__ int s_last;
    const int b = blockIdx.x / HCTA;
    const int c = blockIdx.x % HCTA;
    const int tid = threadIdx.x;
    for (int i = tid; i < NBIN; i += HTHR) sh[i] = 0u;
    __syncthreads();
    const int CHUNK = NA / HCTA / 4;
    const float4* o4 = (const float4*)(obj + (size_t)b * NA) + (size_t)c * CHUNK;
    for (int i = tid; i < CHUNK; i += HTHR) {
        float4 v = o4[i];
        atomicAdd(&sh[mapf(v.x) >> BSHIFT], 1u);
        atomicAdd(&sh[mapf(v.y) >> BSHIFT], 1u);
        atomicAdd(&sh[mapf(v.z) >> BSHIFT], 1u);
        atomicAdd(&sh[mapf(v.w) >> BSHIFT], 1u);
    }
    __syncthreads();
    for (int i = tid; i < NBIN; i += HTHR) {
        unsigned cnt = sh[i];
        if (cnt) atomicAdd(&g_hist[b][i], cnt);
    }
    // last CTA of this batch runs the suffix scan
    __threadfence();
    if (tid == 0) s_last = (atomicAdd(&g_done[b], 1) == HCTA - 1) ? 1 : 0;
    __syncthreads();
    if (!s_last) return;

    __shared__ unsigned ssum[HTHR];
    const int CW = NBIN / HTHR;   // 64
    const int bi = tid * CW;
    unsigned loc[CW];
    unsigned csum = 0;
    #pragma unroll
    for (int k = 0; k < CW; ++k) {
        loc[k] = __ldcg(&g_hist[b][bi + k]);
        csum += loc[k];
    }
    unsigned orig = csum;
    ssum[tid] = csum;
    __syncthreads();
    for (int d = 1; d < HTHR; d <<= 1) {
        unsigned v = (tid + d < HTHR) ? ssum[tid + d] : 0u;
        __syncthreads();
        ssum[tid] += v;
        __syncthreads();
    }
    unsigned run = ssum[tid] - orig;   // count strictly above this chunk
    for (int k = CW - 1; k >= 0; --k) {
        int bin = bi + k;
        g_base[b][bin] = (int)run;
        unsigned nb2 = run + loc[k];
        if (run < PRE && nb2 >= PRE) {
            g_selbin[b] = (unsigned)bin;
            g_cc[b] = (int)(nb2 < KCAP ? nb2 : KCAP);
        }
        run = nb2;
    }
}

// ================= K2: binned scatter of candidates =================
__global__ void __launch_bounds__(STHR) k_scatter(const float* __restrict__ obj) {
    const int b = blockIdx.x / SCTA;
    const int c = blockIdx.x % SCTA;
    const unsigned T = g_selbin[b] << BSHIFT;
    const int CHUNK = NA / SCTA / 4;
    const float4* o4 = (const float4*)(obj + (size_t)b * NA) + (size_t)c * CHUNK;
    for (int i = threadIdx.x; i < CHUNK; i += STHR) {
        float4 v = o4[i];
        unsigned uu[4] = {mapf(v.x), mapf(v.y), mapf(v.z), mapf(v.w)};
        int e0 = (c * CHUNK + i) * 4;
        #pragma unroll
        for (int q = 0; q < 4; ++q) {
            if (uu[q] >= T) {
                int bin = uu[q] >> BSHIFT;
                int slot = g_base[b][bin] + (int)atomicAdd(&g_bincnt[b][bin], 1u);
                if (slot < KCAP)
                    g_keys2[b][slot] =
                        ((unsigned long long)uu[q] << 32) | (unsigned)(~(e0 + q));
            }
        }
    }
}

// ================= K3: two-level exact rank + decode + scatter =================
__global__ void __launch_bounds__(RTHR) k_rank(
    const float* __restrict__ reg, const float* __restrict__ anc)
{
    const int b = blockIdx.x / RCTA;
    const int c = blockIdx.x % RCTA;
    int cc = g_cc[b];
    const int s = c * RTHR + threadIdx.x;
    if (s >= cc) return;

    const unsigned long long me = g_keys2[b][s];
    const unsigned u = (unsigned)(me >> 32);
    const int bin = (int)(u >> BSHIFT);
    const int lo = g_base[b][bin];
    int hi = lo + (int)g_hist[b][bin];
    if (hi > cc) hi = cc;
    int rank = lo;
    const unsigned long long* kb = &g_keys2[b][0];
    int t = lo;
    for (; t + 4 <= hi; t += 4) {
        unsigned long long k0 = kb[t], k1 = kb[t + 1], k2 = kb[t + 2], k3 = kb[t + 3];
        rank += (k0 > me) + (k1 > me) + (k2 > me) + (k3 > me);
    }
    for (; t < hi; ++t) rank += (kb[t] > me);

    if (rank < PRE) {
        int idx = (int)(~(unsigned)(me & 0xFFFFFFFFull));
        const float* rg = reg + ((size_t)b * NA + idx) * 7;
        const float* an = anc + ((size_t)b * NA + idx) * 7;
        float bx[7];
        decode_box(rg, an, bx);
        #pragma unroll
        for (int q = 0; q < 7; ++q) g_box[b][rank][q] = bx[q];
        g_score[b][rank] = 1.0f / (1.0f + expf(-unmapf(u)));
        float sx = fmaxf(bx[3], AUG);
        float sy = fmaxf(bx[4], AUG);
        float sz = fmaxf(bx[5], AUG);
        g_geoA[b][rank] = make_float4(bx[0] - sx * 0.5f, bx[0] + sx * 0.5f,
                                      bx[1] - sy * 0.5f, bx[1] + sy * 0.5f);
        g_geoB[b][rank] = make_float4(bx[2], bx[2] + sz, sx * sy * sz, 0.f);
    }
}

// ================= K4: chip-wide conflict-pair discovery (vectorized) =================
#define JBLK 32
#define ICHK 4
__global__ void __launch_bounds__(128) k_pairs() {
    const int bx = blockIdx.x;
    const int ic = bx & (ICHK - 1);
    const int jb = (bx >> 2) & (JBLK - 1);
    const int b = bx >> 7;
    const int tid = threadIdx.x;

    const int j = jb * 128 + tid;
    const int jmax = min(PRE, jb * 128 + 128);
    const int i_lo = ic * 1024;
    const int i_hi = min(min((ic + 1) * 1024, PRE), jmax);
    if (i_lo >= i_hi) return;

    const bool active = (j < PRE);
    float4 jA = make_float4(0, 0, 0, 0), jB = make_float4(0, 0, 0, 0);
    if (active) {
        jA = g_geoA[b][j];   // lox,hix,loy,hiy
        jB = g_geoB[b][j];   // loz,hiz,vol
    }

    __shared__ float4 sA[128];
    __shared__ float4 sB[128];
    for (int i0 = i_lo; i0 < i_hi; i0 += 128) {
        int ii = i0 + tid;
        if (ii < i_hi) {
            sA[tid] = g_geoA[b][ii];
            sB[tid] = g_geoB[b][ii];
        }
        __syncthreads();
        if (active) {
            int lim = min(128, i_hi - i0);
            for (int k = 0; k < lim; ++k) {
                int i = i0 + k;
                if (i >= j) break;
                float4 a = sA[k];
                float dxx = fminf(jA.y, a.y) - fmaxf(jA.x, a.x);
                if (dxx <= 0.f) continue;
                float dyy = fminf(jA.w, a.w) - fmaxf(jA.z, a.z);
                if (dyy <= 0.f) continue;
                float4 bb = sB[k];
                float dzz = fminf(jB.y, bb.y) - fmaxf(jB.x, bb.x);
                if (dzz <= 0.f) continue;
                float inter = dxx * dyy * dzz;
                float iou = inter / fmaxf(jB.z + bb.z - inter, 1e-8f);
                if (iou > NMS_TH) {
                    int p = atomicAdd(&g_pcnt[b], 1);
                    if (p < PCAP)
                        g_pairs[b][p] = ((unsigned)i << 16) | (unsigned)j;
                }
            }
        }
        __syncthreads();
    }
}

// ================= K5: resolve + output + re-zero scratch =================
__global__ void __launch_bounds__(256) k_final(float* __restrict__ out) {
    const int b = blockIdx.x;
    const int tid = threadIdx.x;
    __shared__ unsigned pr[PCAP];
    __shared__ unsigned keepw[128];
    __shared__ int scan[126];
    __shared__ int order[POST];
    __shared__ int s_nk;

    int m = g_pcnt[b];
    if (m > PCAP) m = PCAP;
    int n2 = 32;
    while (n2 < m) n2 <<= 1;
    for (int i = tid; i < n2; i += 256) pr[i] = (i < m) ? g_pairs[b][i] : 0xFFFFFFFFu;
    __syncthreads();

    for (int k = 2; k <= n2; k <<= 1) {
        for (int jj = k >> 1; jj > 0; jj >>= 1) {
            for (int t = tid; t < n2; t += 256) {
                int ixj = t ^ jj;
                if (ixj > t) {
                    unsigned a = pr[t], c2 = pr[ixj];
                    bool up = ((t & k) == 0);
                    if (up ? (a > c2) : (a < c2)) { pr[t] = c2; pr[ixj] = a; }
                }
            }
            __syncthreads();
        }
    }

    for (int t = tid; t < 128; t += 256) keepw[t] = 0xFFFFFFFFu;
    __syncthreads();

    if (tid == 0) {
        for (int p = 0; p < m; ++p) {
            unsigned u = pr[p];
            int i = (int)(u >> 16);
            int j = (int)(u & 0xFFFFu);
            if ((keepw[i >> 5] >> (i & 31)) & 1u)
                keepw[j >> 5] &= ~(1u << (j & 31));
        }
        int run = 0;
        for (int w = 0; w < 125; ++w) {
            scan[w] = run;
            run += __popc(keepw[w]);
        }
        s_nk = run < POST ? run : POST;
        g_pcnt[b] = 0;
        g_done[b] = 0;
    }
    __syncthreads();

    if (tid < 125) {
        unsigned w = keepw[tid];
        int base = scan[tid];
        while (w && base < POST) {
            int l = __ffs(w) - 1;
            w &= w - 1;
            order[base] = tid * 32 + l;
            ++base;
        }
    }
    __syncthreads();

    const int nk = s_nk;
    float* outb = out + (size_t)b * POST * 8;
    for (int r = tid; r < POST; r += 256) {
        float row[8];
        if (r < nk) {
            int rr = order[r];
            #pragma unroll
            for (int q = 0; q < 7; ++q) row[q] = g_box[b][rr][q];
            row[7] = g_score[b][rr];
        } else {
            #pragma unroll
            for (int q = 0; q < 8; ++q) row[q] = 0.f;
        }
        float4* o4 = (float4*)(outb + (size_t)r * 8);
        o4[0] = make_float4(row[0], row[1], row[2], row[3]);
        o4[1] = make_float4(row[4], row[5], row[6], row[7]);
    }

    for (int i = tid; i < NBIN; i += 256) {
        g_hist[b][i] = 0u;
        g_bincnt[b][i] = 0u;
    }
}

extern "C" void kernel_launch(void* const* d_in, const int* in_sizes, int n_in,
                              void* d_out, int out_size) {
    const float* obj = (const float*)d_in[0];
    const float* reg = (const float*)d_in[1];
    const float* anc = (const float*)d_in[2];
    float* out = (float*)d_out;

    k_hist<<<NB * HCTA, HTHR>>>(obj);
    k_scatter<<<NB * SCTA, STHR>>>(obj);
    k_rank<<<NB * RCTA, RTHR>>>(reg, anc);
    k_pairs<<<NB * JBLK * ICHK, 128>>>();
    k_final<<<NB, 256>>>(out);
}

// round 9
// speedup vs baseline: 2.2275x; 1.1602x over previous
#include <cuda_runtime.h>
#include <math.h>

#define NB 4
#define NA 262144
#define PRE 4000
#define POST 1000
#define NBIN 16384
#define BSHIFT 18
#define KCAP 8192
#define HCTA 64
#define HTHR 256
#define SCTA 128
#define STHR 256
#define RTHR 256
#define RCTA (KCAP / RTHR)
#define PCAP 8192
#define XBINS 256
#define XORG (-8.0f)
#define XSCL 4.0f

static __device__ const float NMS_TH = 0.3f;
static __device__ const float AUG = 0.2f;

// ---- global scratch (zero-init; k_final re-zeroes everything dirtied) ----
__device__ unsigned g_hist[NB][NBIN];
__device__ unsigned g_bincnt[NB][NBIN];
__device__ int g_base[NB][NBIN];
__device__ unsigned g_selbin[NB];
__device__ int g_cc[NB];
__device__ int g_done[NB];
__device__ unsigned long long g_keys2[NB][KCAP];
__device__ float4 g_geoA[NB][PRE];   // lox, hix, loy, hiy   (by rank)
__device__ float4 g_geoB[NB][PRE];   // loz, hiz, vol, -     (by rank)
__device__ float4 g_sA[NB][PRE];     // spatially sorted copy
__device__ float4 g_sB[NB][PRE];     // .w = rank (int bits)
__device__ unsigned g_xcnt[NB][XBINS];
__device__ int g_xbase[NB][XBINS + 1];
__device__ float g_box[NB][PRE][7];
__device__ float g_score[NB][PRE];
__device__ unsigned g_pairs[NB][PCAP];
__device__ int g_pcnt[NB];

__device__ __forceinline__ unsigned mapf(float v) {
    unsigned u = __float_as_uint(v);
    return (u & 0x80000000u) ? ~u : (u | 0x80000000u);
}
__device__ __forceinline__ float unmapf(unsigned m) {
    return __uint_as_float((m & 0x80000000u) ? (m & 0x7FFFFFFFu) : ~m);
}
__device__ __forceinline__ int xcell(float v) {
    int c = (int)((v - XORG) * XSCL);
    return max(0, min(XBINS - 1, c));
}

__device__ __forceinline__ void decode_box(const float* __restrict__ rg,
                                           const float* __restrict__ an,
                                           float* bx) {
    float xa = an[0], ya = an[1], za = an[2];
    float wa = an[3], la = an[4], ha = an[5], ra = an[6];
    float diag = sqrtf(wa * wa + la * la);
    bx[0] = rg[0] * diag + xa;
    bx[1] = rg[1] * diag + ya;
    bx[2] = rg[2] * ha + za;
    bx[3] = expf(rg[3]) * wa;
    bx[4] = expf(rg[4]) * la;
    bx[5] = expf(rg[5]) * ha;
    bx[6] = rg[6] + ra;
}

// ================= K1: smem histogram + last-CTA inline suffix scan =================
__global__ void __launch_bounds__(HTHR) k_hist(const float* __restrict__ obj) {
    __shared__ unsigned sh[NBIN];
    __shared__ int s_last;
    const int b = blockIdx.x / HCTA;
    const int c = blockIdx.x % HCTA;
    const int tid = threadIdx.x;
    for (int i = tid; i < NBIN; i += HTHR) sh[i] = 0u;
    __syncthreads();
    const int CHUNK = NA / HCTA / 4;
    const float4* o4 = (const float4*)(obj + (size_t)b * NA) + (size_t)c * CHUNK;
    for (int i = tid; i < CHUNK; i += HTHR) {
        float4 v = o4[i];
        atomicAdd(&sh[mapf(v.x) >> BSHIFT], 1u);
        atomicAdd(&sh[mapf(v.y) >> BSHIFT], 1u);
        atomicAdd(&sh[mapf(v.z) >> BSHIFT], 1u);
        atomicAdd(&sh[mapf(v.w) >> BSHIFT], 1u);
    }
    __syncthreads();
    for (int i = tid; i < NBIN; i += HTHR) {
        unsigned cnt = sh[i];
        if (cnt) atomicAdd(&g_hist[b][i], cnt);
    }
    __threadfence();
    if (tid == 0) s_last = (atomicAdd(&g_done[b], 1) == HCTA - 1) ? 1 : 0;
    __syncthreads();
    if (!s_last) return;

    __shared__ unsigned ssum[HTHR];
    const int CW = NBIN / HTHR;   // 64
    const int bi = tid * CW;
    unsigned loc[CW];
    unsigned csum = 0;
    #pragma unroll
    for (int k = 0; k < CW; ++k) {
        loc[k] = __ldcg(&g_hist[b][bi + k]);
        csum += loc[k];
    }
    unsigned orig = csum;
    ssum[tid] = csum;
    __syncthreads();
    for (int d = 1; d < HTHR; d <<= 1) {
        unsigned v = (tid + d < HTHR) ? ssum[tid + d] : 0u;
        __syncthreads();
        ssum[tid] += v;
        __syncthreads();
    }
    unsigned run = ssum[tid] - orig;
    for (int k = CW - 1; k >= 0; --k) {
        int bin = bi + k;
        g_base[b][bin] = (int)run;
        unsigned nb2 = run + loc[k];
        if (run < PRE && nb2 >= PRE) {
            g_selbin[b] = (unsigned)bin;
            g_cc[b] = (int)(nb2 < KCAP ? nb2 : KCAP);
        }
        run = nb2;
    }
}

// ================= K2: binned scatter of candidates =================
__global__ void __launch_bounds__(STHR) k_scatter(const float* __restrict__ obj) {
    const int b = blockIdx.x / SCTA;
    const int c = blockIdx.x % SCTA;
    const unsigned T = g_selbin[b] << BSHIFT;
    const int CHUNK = NA / SCTA / 4;
    const float4* o4 = (const float4*)(obj + (size_t)b * NA) + (size_t)c * CHUNK;
    for (int i = threadIdx.x; i < CHUNK; i += STHR) {
        float4 v = o4[i];
        unsigned uu[4] = {mapf(v.x), mapf(v.y), mapf(v.z), mapf(v.w)};
        int e0 = (c * CHUNK + i) * 4;
        #pragma unroll
        for (int q = 0; q < 4; ++q) {
            if (uu[q] >= T) {
                int bin = uu[q] >> BSHIFT;
                int slot = g_base[b][bin] + (int)atomicAdd(&g_bincnt[b][bin], 1u);
                if (slot < KCAP)
                    g_keys2[b][slot] =
                        ((unsigned long long)uu[q] << 32) | (unsigned)(~(e0 + q));
            }
        }
    }
}

// ================= K3: two-level exact rank + decode + x-cell count =================
__global__ void __launch_bounds__(RTHR) k_rank(
    const float* __restrict__ reg, const float* __restrict__ anc)
{
    const int b = blockIdx.x / RCTA;
    const int c = blockIdx.x % RCTA;
    int cc = g_cc[b];
    const int s = c * RTHR + threadIdx.x;
    if (s >= cc) return;

    const unsigned long long me = g_keys2[b][s];
    const unsigned u = (unsigned)(me >> 32);
    const int bin = (int)(u >> BSHIFT);
    const int lo = g_base[b][bin];
    int hi = lo + (int)g_hist[b][bin];
    if (hi > cc) hi = cc;
    int rank = lo;
    const unsigned long long* kb = &g_keys2[b][0];
    int t = lo;
    for (; t + 4 <= hi; t += 4) {
        unsigned long long k0 = kb[t], k1 = kb[t + 1], k2 = kb[t + 2], k3 = kb[t + 3];
        rank += (k0 > me) + (k1 > me) + (k2 > me) + (k3 > me);
    }
    for (; t < hi; ++t) rank += (kb[t] > me);

    if (rank < PRE) {
        int idx = (int)(~(unsigned)(me & 0xFFFFFFFFull));
        const float* rg = reg + ((size_t)b * NA + idx) * 7;
        const float* an = anc + ((size_t)b * NA + idx) * 7;
        float bx[7];
        decode_box(rg, an, bx);
        #pragma unroll
        for (int q = 0; q < 7; ++q) g_box[b][rank][q] = bx[q];
        g_score[b][rank] = 1.0f / (1.0f + expf(-unmapf(u)));
        float sx = fmaxf(bx[3], AUG);
        float sy = fmaxf(bx[4], AUG);
        float sz = fmaxf(bx[5], AUG);
        float lox = bx[0] - sx * 0.5f;
        g_geoA[b][rank] = make_float4(lox, bx[0] + sx * 0.5f,
                                      bx[1] - sy * 0.5f, bx[1] + sy * 0.5f);
        g_geoB[b][rank] = make_float4(bx[2], bx[2] + sz, sx * sy * sz, 0.f);
        atomicAdd(&g_xcnt[b][xcell(lox)], 1u);
    }
}

// ================= K4: x-cell prefix sum + spatial scatter =================
__global__ void __launch_bounds__(256) k_cells() {
    const int b = blockIdx.x;
    const int tid = threadIdx.x;
    __shared__ int s_base[XBINS + 1];
    __shared__ unsigned s_val[XBINS];
    __shared__ unsigned s_cnt2[XBINS];

    unsigned cnt = g_xcnt[b][tid];
    s_val[tid] = cnt;
    s_cnt2[tid] = 0u;
    for (int d = 1; d < XBINS; d <<= 1) {
        __syncthreads();
        unsigned v = (tid >= d) ? s_val[tid - d] : 0u;
        __syncthreads();
        s_val[tid] += v;
    }
    __syncthreads();
    s_base[tid] = (int)(s_val[tid] - cnt);   // exclusive
    if (tid == XBINS - 1) s_base[XBINS] = (int)s_val[XBINS - 1];
    __syncthreads();

    for (int r = tid; r < PRE; r += 256) {
        float4 a = g_geoA[b][r];
        int cell = xcell(a.x);
        int pos = s_base[cell] + (int)atomicAdd(&s_cnt2[cell], 1u);
        g_sA[b][pos] = a;
        float4 bb = g_geoB[b][r];
        bb.w = __int_as_float(r);
        g_sB[b][pos] = bb;
    }
    __syncthreads();
    g_xbase[b][tid] = s_base[tid];
    if (tid == XBINS - 1) g_xbase[b][XBINS] = s_base[XBINS];
}

// ================= K5: sweep-line conflict discovery =================
#define PB 16   // CTAs per batch (16*256 = 4096 >= PRE)
__global__ void __launch_bounds__(256) k_pairs2() {
    const int b = blockIdx.x / PB;
    const int s = (blockIdx.x % PB) * 256 + threadIdx.x;
    if (s >= PRE) return;

    const float4 pA = g_sA[b][s];
    const float4 pB = g_sB[b][s];
    const int rp = __float_as_int(pB.w);
    const int cend = xcell(pA.y);
    const int end = g_xbase[b][cend + 1];

    for (int q = s + 1; q < end; ++q) {
        float4 qA = g_sA[b][q];
        float dxx = fminf(pA.y, qA.y) - fmaxf(pA.x, qA.x);
        if (dxx <= 0.f) continue;
        float dyy = fminf(pA.w, qA.w) - fmaxf(pA.z, qA.z);
        if (dyy <= 0.f) continue;
        float4 qB = g_sB[b][q];
        float dzz = fminf(pB.y, qB.y) - fmaxf(pB.x, qB.x);
        if (dzz <= 0.f) continue;
        float inter = dxx * dyy * dzz;
        float iou = inter / fmaxf(pB.z + qB.z - inter, 1e-8f);
        if (iou > NMS_TH) {
            int rq = __float_as_int(qB.w);
            int i = min(rp, rq), j = max(rp, rq);
            int p = atomicAdd(&g_pcnt[b], 1);
            if (p < PCAP) g_pairs[b][p] = ((unsigned)i << 16) | (unsigned)j;
        }
    }
}

// ================= K6: resolve + output + re-zero scratch =================
__global__ void __launch_bounds__(256) k_final(float* __restrict__ out) {
    const int b = blockIdx.x;
    const int tid = threadIdx.x;
    __shared__ unsigned pr[PCAP];
    __shared__ unsigned keepw[128];
    __shared__ int scan[126];
    __shared__ int order[POST];
    __shared__ int s_nk;

    int m = g_pcnt[b];
    if (m > PCAP) m = PCAP;
    int n2 = 32;
    while (n2 < m) n2 <<= 1;
    for (int i = tid; i < n2; i += 256) pr[i] = (i < m) ? g_pairs[b][i] : 0xFFFFFFFFu;
    __syncthreads();

    for (int k = 2; k <= n2; k <<= 1) {
        for (int jj = k >> 1; jj > 0; jj >>= 1) {
            for (int t = tid; t < n2; t += 256) {
                int ixj = t ^ jj;
                if (ixj > t) {
                    unsigned a = pr[t], c2 = pr[ixj];
                    bool up = ((t & k) == 0);
                    if (up ? (a > c2) : (a < c2)) { pr[t] = c2; pr[ixj] = a; }
                }
            }
            __syncthreads();
        }
    }

    for (int t = tid; t < 128; t += 256) keepw[t] = 0xFFFFFFFFu;
    __syncthreads();

    if (tid == 0) {
        for (int p = 0; p < m; ++p) {
            unsigned u = pr[p];
            int i = (int)(u >> 16);
            int j = (int)(u & 0xFFFFu);
            if ((keepw[i >> 5] >> (i & 31)) & 1u)
                keepw[j >> 5] &= ~(1u << (j & 31));
        }
        int run = 0;
        for (int w = 0; w < 125; ++w) {
            scan[w] = run;
            run += __popc(keepw[w]);
        }
        s_nk = run < POST ? run : POST;
        g_pcnt[b] = 0;
        g_done[b] = 0;
    }
    __syncthreads();

    if (tid < 125) {
        unsigned w = keepw[tid];
        int base = scan[tid];
        while (w && base < POST) {
            int l = __ffs(w) - 1;
            w &= w - 1;
            order[base] = tid * 32 + l;
            ++base;
        }
    }
    __syncthreads();

    const int nk = s_nk;
    float* outb = out + (size_t)b * POST * 8;
    for (int r = tid; r < POST; r += 256) {
        float row[8];
        if (r < nk) {
            int rr = order[r];
            #pragma unroll
            for (int q = 0; q < 7; ++q) row[q] = g_box[b][rr][q];
            row[7] = g_score[b][rr];
        } else {
            #pragma unroll
            for (int q = 0; q < 8; ++q) row[q] = 0.f;
        }
        float4* o4 = (float4*)(outb + (size_t)r * 8);
        o4[0] = make_float4(row[0], row[1], row[2], row[3]);
        o4[1] = make_float4(row[4], row[5], row[6], row[7]);
    }

    for (int i = tid; i < NBIN; i += 256) {
        g_hist[b][i] = 0u;
        g_bincnt[b][i] = 0u;
    }
    if (tid < XBINS) g_xcnt[b][tid] = 0u;
}

extern "C" void kernel_launch(void* const* d_in, const int* in_sizes, int n_in,
                              void* d_out, int out_size) {
    const float* obj = (const float*)d_in[0];
    const float* reg = (const float*)d_in[1];
    const float* anc = (const float*)d_in[2];
    float* out = (float*)d_out;

    k_hist<<<NB * HCTA, HTHR>>>(obj);
    k_scatter<<<NB * SCTA, STHR>>>(obj);
    k_rank<<<NB * RCTA, RTHR>>>(reg, anc);
    k_cells<<<NB, XBINS>>>();
    k_pairs2<<<NB * PB, 256>>>();
    k_final<<<NB, 256>>>(out);
}